// round 9
// baseline (speedup 1.0000x reference)
#include <cuda_runtime.h>
#include <cuda_fp16.h>
#include <cstdint>

#define DIMC   1024
#define HEADS  16
#define NTOK   49
#define BATCH  1024
#define MROWS  (BATCH * NTOK)   // 50176
#define SCALE  0.125f

// ---------------- half scratch ----------------
__device__ __half g_A[(size_t)MROWS * DIMC];
__device__ __half g_B[(size_t)MROWS * DIMC];
__device__ __half g_Q[(size_t)MROWS * DIMC];
__device__ __half g_K[(size_t)MROWS * DIMC];
__device__ __half g_V[(size_t)MROWS * DIMC];
__device__ __half g_Wh[4 * (size_t)DIMC * DIMC];
__device__ float  g_bias[HEADS * NTOK * NTOK];

// ---------------- conversions ----------------
__global__ void f2h_inputs(const float* __restrict__ a, const float* __restrict__ b) {
    const int n4 = MROWS * DIMC / 4;
    int i = blockIdx.x * blockDim.x + threadIdx.x;
    int stride = gridDim.x * blockDim.x;
    for (int t = i; t < n4; t += stride) {
        float4 v = ((const float4*)a)[t];
        __half2 h0 = __floats2half2_rn(v.x, v.y), h1 = __floats2half2_rn(v.z, v.w);
        ((uint2*)g_A)[t] = make_uint2(*(uint32_t*)&h0, *(uint32_t*)&h1);
        v = ((const float4*)b)[t];
        h0 = __floats2half2_rn(v.x, v.y); h1 = __floats2half2_rn(v.z, v.w);
        ((uint2*)g_B)[t] = make_uint2(*(uint32_t*)&h0, *(uint32_t*)&h1);
    }
}

__global__ void f2h_weights_bias(const float* __restrict__ w0, const float* __restrict__ w1,
                                 const float* __restrict__ w2, const float* __restrict__ w3,
                                 const float* __restrict__ bt, const int* __restrict__ ri) {
    const float* srcs[4] = {w0, w1, w2, w3};
    const int n4 = DIMC * DIMC / 4;
    int i = blockIdx.x * blockDim.x + threadIdx.x;
    int stride = gridDim.x * blockDim.x;
#pragma unroll
    for (int m = 0; m < 4; ++m) {
        const float4* src = (const float4*)srcs[m];
        uint2* dst = (uint2*)(g_Wh + (size_t)m * DIMC * DIMC);
        for (int t = i; t < n4; t += stride) {
            float4 v = src[t];
            __half2 h0 = __floats2half2_rn(v.x, v.y), h1 = __floats2half2_rn(v.z, v.w);
            dst[t] = make_uint2(*(uint32_t*)&h0, *(uint32_t*)&h1);
        }
    }
    for (int t = i; t < NTOK * NTOK; t += stride) {
        int idx = ri[t] * HEADS;
#pragma unroll
        for (int h = 0; h < HEADS; ++h)
            g_bias[h * (NTOK * NTOK) + t] = bt[idx + h];
    }
}

// ---------------- asm helpers ----------------
__device__ __forceinline__ void cp_async16(uint32_t saddr, const void* g) {
    asm volatile("cp.async.cg.shared.global [%0], [%1], 16;\n" :: "r"(saddr), "l"(g) : "memory");
}
__device__ __forceinline__ void cp_commit() { asm volatile("cp.async.commit_group;\n" ::: "memory"); }
__device__ __forceinline__ void cp_wait1() { asm volatile("cp.async.wait_group 1;\n" ::: "memory"); }

__device__ __forceinline__ void mma_f16(float c[4], uint32_t a0, uint32_t a1, uint32_t a2,
                                        uint32_t a3, uint32_t b0, uint32_t b1) {
    asm volatile(
        "mma.sync.aligned.m16n8k16.row.col.f32.f16.f16.f32 "
        "{%0,%1,%2,%3}, {%4,%5,%6,%7}, {%8,%9}, {%0,%1,%2,%3};\n"
        : "+f"(c[0]), "+f"(c[1]), "+f"(c[2]), "+f"(c[3])
        : "r"(a0), "r"(a1), "r"(a2), "r"(a3), "r"(b0), "r"(b1));
}

__device__ __forceinline__ void ldsm_x4(uint32_t& r0, uint32_t& r1, uint32_t& r2, uint32_t& r3,
                                        uint32_t addr) {
    asm volatile("ldmatrix.sync.aligned.m8n8.x4.shared.b16 {%0,%1,%2,%3}, [%4];"
                 : "=r"(r0), "=r"(r1), "=r"(r2), "=r"(r3) : "r"(addr));
}
__device__ __forceinline__ void ldsm_x4_t(uint32_t& r0, uint32_t& r1, uint32_t& r2, uint32_t& r3,
                                          uint32_t addr) {
    asm volatile("ldmatrix.sync.aligned.m8n8.x4.trans.shared.b16 {%0,%1,%2,%3}, [%4];"
                 : "=r"(r0), "=r"(r1), "=r"(r2), "=r"(r3) : "r"(addr));
}

// ---------------- FP16 GEMM: 128x128 tile, 4 warps, 64x64 warp tile ----------------
#define BM 128
#define BN 128
#define BKH 64
#define NKT (DIMC / BKH)           // 16
#define TILE (BM * 128)            // 16384 B
#define SLOT (2 * TILE)            // 32768 B
#define SMEMSZ (3 * SLOT)          // 98304 B

__global__ __launch_bounds__(128, 2) void gemm_h(
    const float* __restrict__ bias, float* __restrict__ Yf,
    int xsel, int wsel, int ysel)
{
    extern __shared__ __align__(128) uint8_t smem[];
    const __half* X = xsel ? g_B : g_A;
    const __half* W = g_Wh + (size_t)wsel * DIMC * DIMC;
    __half* Yh = (ysel == 1) ? g_Q : (ysel == 2) ? g_K : g_V;

    const int tid = threadIdx.x, wid = tid >> 5, lane = tid & 31;
    const int wm = wid >> 1, wn = wid & 1;
    const int m0 = blockIdx.y * BM, n0 = blockIdx.x * BN;
    const uint32_t sbase = (uint32_t)__cvta_generic_to_shared(smem);

    float acc[4][8][4];
#pragma unroll
    for (int a = 0; a < 4; ++a)
#pragma unroll
        for (int b = 0; b < 8; ++b)
#pragma unroll
            for (int c = 0; c < 4; ++c) acc[a][b][c] = 0.f;

    // ldmatrix addresses (validated scheme, warp tile 64x64)
    const int lane_r = lane & 15;
    const int halfA  = lane >> 4;
    const int swA    = lane_r & 7;
    uint32_t offA[4];
#pragma unroll
    for (int mi = 0; mi < 4; ++mi)
        offA[mi] = (uint32_t)((wm * 64 + mi * 16 + lane_r) * 128);

    const int quad = lane >> 3;
    const int swB  = lane & 7;
    const int gselB = quad & 1;
    uint32_t offB[4];
#pragma unroll
    for (int pi = 0; pi < 4; ++pi)
        offB[pi] = (uint32_t)((wn * 64 + (2 * pi + (quad >> 1)) * 8 + (lane & 7)) * 128);

    // stage loader: thread tid loads row tid of A and of B (8 granules each)
    const int swr = tid & 7;
    auto load_stage = [&](int slot, int kt) {
        const __half* xa = X + (size_t)(m0 + tid) * DIMC + kt * BKH;
        const __half* xb = W + (size_t)(n0 + tid) * DIMC + kt * BKH;
        uint32_t sa = sbase + slot * SLOT + tid * 128;
        uint32_t sb = sa + TILE;
#pragma unroll
        for (int g = 0; g < 8; ++g) {
            uint32_t off = (uint32_t)((g ^ swr) << 4);
            cp_async16(sa + off, xa + g * 8);
            cp_async16(sb + off, xb + g * 8);
        }
        cp_commit();
    };

    load_stage(0, 0);
    load_stage(1, 1);

    const int r8 = lane >> 2, cp2 = (lane & 3) * 2;

    uint32_t afr[2][4][4], bfr[2][4][4];
    auto load_frags = [&](int buf, int ks, uint32_t baseA, uint32_t baseB) {
        const uint32_t gA = (uint32_t)(((ks * 2 + halfA) ^ swA) << 4);
        const uint32_t gB = (uint32_t)(((ks * 2 + gselB) ^ swB) << 4);
#pragma unroll
        for (int mi = 0; mi < 4; ++mi)
            ldsm_x4(afr[buf][mi][0], afr[buf][mi][1], afr[buf][mi][2], afr[buf][mi][3],
                    baseA + offA[mi] + gA);
#pragma unroll
        for (int pi = 0; pi < 4; ++pi)
            ldsm_x4(bfr[buf][pi][0], bfr[buf][pi][1], bfr[buf][pi][2], bfr[buf][pi][3],
                    baseB + offB[pi] + gB);
    };

    for (int kt = 0; kt < NKT; ++kt) {
        cp_wait1();
        __syncthreads();
        if (kt + 2 < NKT) load_stage((kt + 2) % 3, kt + 2);

        const uint32_t baseA = sbase + (kt % 3) * SLOT;
        const uint32_t baseB = baseA + TILE;

        load_frags(0, 0, baseA, baseB);
#pragma unroll
        for (int ks = 0; ks < 4; ++ks) {
            if (ks < 3) load_frags((ks + 1) & 1, ks + 1, baseA, baseB);
            const int cb = ks & 1;
#pragma unroll
            for (int mi = 0; mi < 4; ++mi)
#pragma unroll
                for (int pi = 0; pi < 4; ++pi) {
                    mma_f16(acc[mi][2 * pi],     afr[cb][mi][0], afr[cb][mi][1],
                            afr[cb][mi][2], afr[cb][mi][3], bfr[cb][pi][0], bfr[cb][pi][1]);
                    mma_f16(acc[mi][2 * pi + 1], afr[cb][mi][0], afr[cb][mi][1],
                            afr[cb][mi][2], afr[cb][mi][3], bfr[cb][pi][2], bfr[cb][pi][3]);
                }
        }
    }

    // epilogue
#pragma unroll
    for (int mi = 0; mi < 4; ++mi) {
        int r = m0 + wm * 64 + mi * 16 + r8;
#pragma unroll
        for (int ni = 0; ni < 8; ++ni) {
            int cc = n0 + wn * 64 + ni * 8 + cp2;
            float b0 = bias[cc], b1 = bias[cc + 1];
            float v0 = acc[mi][ni][0] + b0, v1 = acc[mi][ni][1] + b1;
            float v2 = acc[mi][ni][2] + b0, v3 = acc[mi][ni][3] + b1;
            if (ysel == 0) {
                *(float2*)&Yf[(size_t)r * DIMC + cc]       = make_float2(v0, v1);
                *(float2*)&Yf[(size_t)(r + 8) * DIMC + cc] = make_float2(v2, v3);
            } else {
                __half2 h0 = __floats2half2_rn(v0, v1);
                __half2 h1 = __floats2half2_rn(v2, v3);
                *(__half2*)&Yh[(size_t)r * DIMC + cc]       = h0;
                *(__half2*)&Yh[(size_t)(r + 8) * DIMC + cc] = h1;
            }
        }
    }
}

// ---------------- tensor-core windowed attention (unchanged, round 7) ----------------
__global__ __launch_bounds__(128) void attn_mma() {
    __shared__ __align__(128) uint8_t sQ[64 * 128];
    __shared__ __align__(128) uint8_t sK[64 * 128];
    __shared__ __align__(128) uint8_t sV[64 * 128];
    __shared__ float sS[64 * 66];

    const int b = blockIdx.x, h = blockIdx.y;
    const int tid = threadIdx.x, warp = tid >> 5, lane = tid & 31;
    const size_t base = (size_t)(b * NTOK) * DIMC + h * 64;

    const uint32_t qb = (uint32_t)__cvta_generic_to_shared(sQ);
    const uint32_t kb = (uint32_t)__cvta_generic_to_shared(sK);
    const uint32_t vb = (uint32_t)__cvta_generic_to_shared(sV);

    for (int t = tid; t < NTOK * 8; t += 128) {
        int r = t >> 3, g = t & 7;
        uint32_t off = (uint32_t)(r * 128 + ((g ^ (r & 7)) << 4));
        *(uint4*)(sQ + off) = *(const uint4*)&g_Q[base + (size_t)r * DIMC + g * 8];
        *(uint4*)(sK + off) = *(const uint4*)&g_K[base + (size_t)r * DIMC + g * 8];
        *(uint4*)(sV + off) = *(const uint4*)&g_V[base + (size_t)r * DIMC + g * 8];
    }
    for (int t = tid; t < 15 * 8; t += 128) {
        int r = NTOK + (t >> 3), g = t & 7;
        uint32_t off = (uint32_t)(r * 128 + ((g ^ (r & 7)) << 4));
        *(uint4*)(sV + off) = make_uint4(0, 0, 0, 0);
    }
    __syncthreads();

    const int lane_r = lane & 15, halfA = lane >> 4;
    const int quad = lane >> 3, gsel = quad & 1, rsel = quad >> 1;
    const int r8 = lane >> 2, cp2 = (lane & 3) * 2;
    const int swA = lane_r & 7, sw8 = lane & 7;

    {
        float acc[8][4];
#pragma unroll
        for (int nt = 0; nt < 8; ++nt)
#pragma unroll
            for (int c = 0; c < 4; ++c) acc[nt][c] = 0.f;

        const uint32_t aRowOff = qb + (uint32_t)((16 * warp + lane_r) * 128);
        uint32_t bRowOff[4];
#pragma unroll
        for (int pj = 0; pj < 4; ++pj)
            bRowOff[pj] = kb + (uint32_t)((16 * pj + rsel * 8 + sw8) * 128);

#pragma unroll
        for (int ks = 0; ks < 4; ++ks) {
            uint32_t a0, a1, a2, a3;
            ldsm_x4(a0, a1, a2, a3, aRowOff + (uint32_t)(((ks * 2 + halfA) ^ swA) << 4));
            const uint32_t gB = (uint32_t)(((ks * 2 + gsel) ^ sw8) << 4);
#pragma unroll
            for (int pj = 0; pj < 4; ++pj) {
                uint32_t b0, b1, b2, b3;
                ldsm_x4(b0, b1, b2, b3, bRowOff[pj] + gB);
                mma_f16(acc[2 * pj],     a0, a1, a2, a3, b0, b1);
                mma_f16(acc[2 * pj + 1], a0, a1, a2, a3, b2, b3);
            }
        }

        const float* gbias = g_bias + h * (NTOK * NTOK);
        const int i0 = 16 * warp + r8, i1 = i0 + 8;
#pragma unroll
        for (int nt = 0; nt < 8; ++nt) {
            int j0 = nt * 8 + cp2, j1 = j0 + 1;
            float v0 = -1e30f, v1 = -1e30f, v2 = -1e30f, v3 = -1e30f;
            if (i0 < NTOK) {
                if (j0 < NTOK) v0 = acc[nt][0] * SCALE + gbias[i0 * NTOK + j0];
                if (j1 < NTOK) v1 = acc[nt][1] * SCALE + gbias[i0 * NTOK + j1];
            }
            if (i1 < NTOK) {
                if (j0 < NTOK) v2 = acc[nt][2] * SCALE + gbias[i1 * NTOK + j0];
                if (j1 < NTOK) v3 = acc[nt][3] * SCALE + gbias[i1 * NTOK + j1];
            }
            sS[i0 * 66 + j0] = v0; sS[i0 * 66 + j1] = v1;
            sS[i1 * 66 + j0] = v2; sS[i1 * 66 + j1] = v3;
        }
    }
    __syncthreads();

    for (int i = warp; i < NTOK; i += 4) {
        float v1 = sS[i * 66 + lane];
        float v2 = sS[i * 66 + lane + 32];
        float m = fmaxf(v1, v2);
#pragma unroll
        for (int o = 16; o > 0; o >>= 1) m = fmaxf(m, __shfl_xor_sync(0xFFFFFFFFu, m, o));
        float e1 = __expf(v1 - m), e2 = __expf(v2 - m);
        float s = e1 + e2;
#pragma unroll
        for (int o = 16; o > 0; o >>= 1) s += __shfl_xor_sync(0xFFFFFFFFu, s, o);
        float inv = 1.f / s;
        __half p1 = __float2half_rn(e1 * inv);
        __half p2 = __float2half_rn(e2 * inv);
        int j1 = lane, j2 = lane + 32;
        *(__half*)(sQ + i * 128 + (((j1 >> 3) ^ (i & 7)) << 4) + (j1 & 7) * 2) = p1;
        *(__half*)(sQ + i * 128 + (((j2 >> 3) ^ (i & 7)) << 4) + (j2 & 7) * 2) = p2;
    }
    __syncthreads();

    {
        float acc[8][4];
#pragma unroll
        for (int nt = 0; nt < 8; ++nt)
#pragma unroll
            for (int c = 0; c < 4; ++c) acc[nt][c] = 0.f;

        const uint32_t aRowOff = qb + (uint32_t)((16 * warp + lane_r) * 128);

#pragma unroll
        for (int ks = 0; ks < 4; ++ks) {
            uint32_t a0, a1, a2, a3;
            ldsm_x4(a0, a1, a2, a3, aRowOff + (uint32_t)(((ks * 2 + halfA) ^ swA) << 4));
            const uint32_t tRow = (uint32_t)(16 * ks + 8 * gsel + sw8);
            const uint32_t vRow = vb + tRow * 128;
#pragma unroll
            for (int pj = 0; pj < 4; ++pj) {
                uint32_t b0, b1, b2, b3;
                ldsm_x4_t(b0, b1, b2, b3, vRow + (uint32_t)((((2 * pj + rsel) ^ sw8) << 4)));
                mma_f16(acc[2 * pj],     a0, a1, a2, a3, b0, b1);
                mma_f16(acc[2 * pj + 1], a0, a1, a2, a3, b2, b3);
            }
        }

        const int i0 = 16 * warp + r8, i1 = i0 + 8;
#pragma unroll
        for (int nt = 0; nt < 8; ++nt) {
            int d = nt * 8 + cp2;
            if (i0 < NTOK) {
                __half2 o = __floats2half2_rn(acc[nt][0], acc[nt][1]);
                *(__half2*)&g_B[base + (size_t)i0 * DIMC + d] = o;
            }
            if (i1 < NTOK) {
                __half2 o = __floats2half2_rn(acc[nt][2], acc[nt][3]);
                *(__half2*)&g_B[base + (size_t)i1 * DIMC + d] = o;
            }
        }
    }
}

// ---------------- launch ----------------
extern "C" void kernel_launch(void* const* d_in, const int* in_sizes, int n_in,
                              void* d_out, int out_size) {
    const float* landmark = (const float*)d_in[0];
    const float* image    = (const float*)d_in[1];
    const float* Wq = (const float*)d_in[2];
    const float* bq = (const float*)d_in[3];
    const float* Wk = (const float*)d_in[4];
    const float* bk = (const float*)d_in[5];
    const float* Wv = (const float*)d_in[6];
    const float* bv = (const float*)d_in[7];
    const float* Wo = (const float*)d_in[8];
    const float* bo = (const float*)d_in[9];
    const float* bt = (const float*)d_in[10];
    const int*   ri = (const int*)d_in[11];
    float* out = (float*)d_out;

    cudaFuncSetAttribute(gemm_h, cudaFuncAttributeMaxDynamicSharedMemorySize, SMEMSZ);

    dim3 gg(DIMC / BN, MROWS / BM);   // (8, 392)

    f2h_inputs<<<8192, 256>>>(landmark, image);
    f2h_weights_bias<<<512, 256>>>(Wq, Wk, Wv, Wo, bt, ri);
    gemm_h<<<gg, 128, SMEMSZ>>>(bq, nullptr, 0, 0, 1);   // Q
    gemm_h<<<gg, 128, SMEMSZ>>>(bk, nullptr, 1, 1, 2);   // K
    gemm_h<<<gg, 128, SMEMSZ>>>(bv, nullptr, 1, 2, 3);   // V
    attn_mma<<<dim3(BATCH, HEADS), 128>>>();
    gemm_h<<<gg, 128, SMEMSZ>>>(bo, out, 1, 3, 0);       // O
}

// round 10
// speedup vs baseline: 1.3648x; 1.3648x over previous
#include <cuda_runtime.h>
#include <cuda_fp16.h>
#include <cstdint>

#define DIMC   1024
#define HEADS  16
#define NTOK   49
#define BATCH  1024
#define MROWS  (BATCH * NTOK)   // 50176
#define SCALE  0.125f

// ---------------- half scratch ----------------
__device__ __half g_A[(size_t)MROWS * DIMC];
__device__ __half g_B[(size_t)MROWS * DIMC];
__device__ __half g_Q[(size_t)MROWS * DIMC];
__device__ __half g_K[(size_t)MROWS * DIMC];
__device__ __half g_V[(size_t)MROWS * DIMC];
__device__ __half g_Wh[4 * (size_t)DIMC * DIMC];
__device__ float  g_bias[HEADS * NTOK * NTOK];

// ---------------- conversions ----------------
__global__ void f2h_inputs(const float* __restrict__ a, const float* __restrict__ b) {
    const int n4 = MROWS * DIMC / 4;
    int i = blockIdx.x * blockDim.x + threadIdx.x;
    int stride = gridDim.x * blockDim.x;
    for (int t = i; t < n4; t += stride) {
        float4 v = ((const float4*)a)[t];
        __half2 h0 = __floats2half2_rn(v.x, v.y), h1 = __floats2half2_rn(v.z, v.w);
        ((uint2*)g_A)[t] = make_uint2(*(uint32_t*)&h0, *(uint32_t*)&h1);
        v = ((const float4*)b)[t];
        h0 = __floats2half2_rn(v.x, v.y); h1 = __floats2half2_rn(v.z, v.w);
        ((uint2*)g_B)[t] = make_uint2(*(uint32_t*)&h0, *(uint32_t*)&h1);
    }
}

__global__ void f2h_weights_bias(const float* __restrict__ w0, const float* __restrict__ w1,
                                 const float* __restrict__ w2, const float* __restrict__ w3,
                                 const float* __restrict__ bt, const int* __restrict__ ri) {
    const float* srcs[4] = {w0, w1, w2, w3};
    const int n4 = DIMC * DIMC / 4;
    int i = blockIdx.x * blockDim.x + threadIdx.x;
    int stride = gridDim.x * blockDim.x;
#pragma unroll
    for (int m = 0; m < 4; ++m) {
        const float4* src = (const float4*)srcs[m];
        uint2* dst = (uint2*)(g_Wh + (size_t)m * DIMC * DIMC);
        for (int t = i; t < n4; t += stride) {
            float4 v = src[t];
            __half2 h0 = __floats2half2_rn(v.x, v.y), h1 = __floats2half2_rn(v.z, v.w);
            dst[t] = make_uint2(*(uint32_t*)&h0, *(uint32_t*)&h1);
        }
    }
    for (int t = i; t < NTOK * NTOK; t += stride) {
        int idx = ri[t] * HEADS;
#pragma unroll
        for (int h = 0; h < HEADS; ++h)
            g_bias[h * (NTOK * NTOK) + t] = bt[idx + h];
    }
}

// ---------------- asm helpers ----------------
__device__ __forceinline__ void cp_async16(uint32_t saddr, const void* g) {
    asm volatile("cp.async.cg.shared.global [%0], [%1], 16;\n" :: "r"(saddr), "l"(g) : "memory");
}
__device__ __forceinline__ void cp_commit() { asm volatile("cp.async.commit_group;\n" ::: "memory"); }
__device__ __forceinline__ void cp_wait1() { asm volatile("cp.async.wait_group 1;\n" ::: "memory"); }

__device__ __forceinline__ void mma_f16(float c[4], uint32_t a0, uint32_t a1, uint32_t a2,
                                        uint32_t a3, uint32_t b0, uint32_t b1) {
    asm volatile(
        "mma.sync.aligned.m16n8k16.row.col.f32.f16.f16.f32 "
        "{%0,%1,%2,%3}, {%4,%5,%6,%7}, {%8,%9}, {%0,%1,%2,%3};\n"
        : "+f"(c[0]), "+f"(c[1]), "+f"(c[2]), "+f"(c[3])
        : "r"(a0), "r"(a1), "r"(a2), "r"(a3), "r"(b0), "r"(b1));
}

__device__ __forceinline__ void ldsm_x4(uint32_t& r0, uint32_t& r1, uint32_t& r2, uint32_t& r3,
                                        uint32_t addr) {
    asm volatile("ldmatrix.sync.aligned.m8n8.x4.shared.b16 {%0,%1,%2,%3}, [%4];"
                 : "=r"(r0), "=r"(r1), "=r"(r2), "=r"(r3) : "r"(addr));
}
__device__ __forceinline__ void ldsm_x4_t(uint32_t& r0, uint32_t& r1, uint32_t& r2, uint32_t& r3,
                                          uint32_t addr) {
    asm volatile("ldmatrix.sync.aligned.m8n8.x4.trans.shared.b16 {%0,%1,%2,%3}, [%4];"
                 : "=r"(r0), "=r"(r1), "=r"(r2), "=r"(r3) : "r"(addr));
}

// ---------------- FP16 GEMM core (R5/R6 proven shape) ----------------
#define BM 128
#define BN 128
#define BKH 64
#define NKT (DIMC / BKH)           // 16
#define TILE_A (BM * 128)          // 16384 B
#define SLOT (2 * TILE_A)
#define SMEMSZ (3 * SLOT)          // 98304 B

__device__ __forceinline__ void gemm_core(
    const __half* __restrict__ X, const __half* __restrict__ W,
    const float* __restrict__ bias, float* __restrict__ Yf, __half* __restrict__ Yh,
    int m0, int n0, uint8_t* smem)
{
    const int tid = threadIdx.x, wid = tid >> 5, lane = tid & 31;
    const int wm = wid >> 2, wn = wid & 3;
    const uint32_t sbase = (uint32_t)__cvta_generic_to_shared(smem);

    float acc[4][4][4];
#pragma unroll
    for (int a = 0; a < 4; ++a)
#pragma unroll
        for (int b = 0; b < 4; ++b)
#pragma unroll
            for (int c = 0; c < 4; ++c) acc[a][b][c] = 0.f;

    const int lane_r = lane & 15;
    const int halfA  = lane >> 4;
    const int swA    = lane_r & 7;
    uint32_t offA[4];
#pragma unroll
    for (int mi = 0; mi < 4; ++mi)
        offA[mi] = (uint32_t)((wm * 64 + mi * 16 + lane_r) * 128);

    const int quad = lane >> 3;
    const int swB  = lane & 7;
    const int gselB = quad & 1;
    uint32_t offB[2];
#pragma unroll
    for (int pi = 0; pi < 2; ++pi)
        offB[pi] = (uint32_t)((wn * 32 + (2 * pi + (quad >> 1)) * 8 + (lane & 7)) * 128);

    const int row = tid >> 1;
    const int g0 = (tid & 1) * 4;
    const int swr = row & 7;
    auto load_stage = [&](int slot, int kt) {
        const __half* xa = X + (size_t)(m0 + row) * DIMC + kt * BKH;
        const __half* xb = W + (size_t)(n0 + row) * DIMC + kt * BKH;
        uint32_t sa = sbase + slot * SLOT + row * 128;
        uint32_t sb = sa + TILE_A;
#pragma unroll
        for (int q = 0; q < 4; ++q) {
            int g = g0 + q;
            uint32_t off = (uint32_t)((g ^ swr) << 4);
            cp_async16(sa + off, xa + g * 8);
            cp_async16(sb + off, xb + g * 8);
        }
        cp_commit();
    };

    load_stage(0, 0);
    load_stage(1, 1);

    const int r8 = lane >> 2, cp2 = (lane & 3) * 2;

    for (int kt = 0; kt < NKT; ++kt) {
        cp_wait1();
        __syncthreads();
        if (kt + 2 < NKT) load_stage((kt + 2) % 3, kt + 2);

        const uint32_t baseA = sbase + (kt % 3) * SLOT;
        const uint32_t baseB = baseA + TILE_A;
#pragma unroll
        for (int ks = 0; ks < 4; ++ks) {
            uint32_t a[4][4], b[2][4];
            const uint32_t gA = (uint32_t)(((ks * 2 + halfA) ^ swA) << 4);
            const uint32_t gB = (uint32_t)(((ks * 2 + gselB) ^ swB) << 4);
#pragma unroll
            for (int mi = 0; mi < 4; ++mi)
                ldsm_x4(a[mi][0], a[mi][1], a[mi][2], a[mi][3], baseA + offA[mi] + gA);
#pragma unroll
            for (int pi = 0; pi < 2; ++pi)
                ldsm_x4(b[pi][0], b[pi][1], b[pi][2], b[pi][3], baseB + offB[pi] + gB);
#pragma unroll
            for (int mi = 0; mi < 4; ++mi) {
                mma_f16(acc[mi][0], a[mi][0], a[mi][1], a[mi][2], a[mi][3], b[0][0], b[0][1]);
                mma_f16(acc[mi][1], a[mi][0], a[mi][1], a[mi][2], a[mi][3], b[0][2], b[0][3]);
                mma_f16(acc[mi][2], a[mi][0], a[mi][1], a[mi][2], a[mi][3], b[1][0], b[1][1]);
                mma_f16(acc[mi][3], a[mi][0], a[mi][1], a[mi][2], a[mi][3], b[1][2], b[1][3]);
            }
        }
    }

#pragma unroll
    for (int mi = 0; mi < 4; ++mi) {
        int r = m0 + wm * 64 + mi * 16 + r8;
#pragma unroll
        for (int ni = 0; ni < 4; ++ni) {
            int cc = n0 + wn * 32 + ni * 8 + cp2;
            float b0 = bias[cc], b1 = bias[cc + 1];
            float v0 = acc[mi][ni][0] + b0, v1 = acc[mi][ni][1] + b1;
            float v2 = acc[mi][ni][2] + b0, v3 = acc[mi][ni][3] + b1;
            if (Yf) {
                *(float2*)&Yf[(size_t)r * DIMC + cc]       = make_float2(v0, v1);
                *(float2*)&Yf[(size_t)(r + 8) * DIMC + cc] = make_float2(v2, v3);
            } else {
                __half2 h0 = __floats2half2_rn(v0, v1);
                __half2 h1 = __floats2half2_rn(v2, v3);
                *(__half2*)&Yh[(size_t)r * DIMC + cc]       = h0;
                *(__half2*)&Yh[(size_t)(r + 8) * DIMC + cc] = h1;
            }
        }
    }
}

// merged Q/K/V projections: blockIdx.z selects the GEMM
__global__ __launch_bounds__(256, 2) void gemm_qkv(
    const float* __restrict__ bq, const float* __restrict__ bk, const float* __restrict__ bv)
{
    extern __shared__ __align__(128) uint8_t smem[];
    const int z = blockIdx.z;
    const __half* X = (z == 0) ? g_A : g_B;
    const __half* W = g_Wh + (size_t)z * DIMC * DIMC;
    __half* Yh = (z == 0) ? g_Q : (z == 1) ? g_K : g_V;
    const float* bias = (z == 0) ? bq : (z == 1) ? bk : bv;
    gemm_core(X, W, bias, nullptr, Yh, blockIdx.y * BM, blockIdx.x * BN, smem);
}

// output projection: fp32 result to d_out
__global__ __launch_bounds__(256, 2) void gemm_o(
    const float* __restrict__ bo, float* __restrict__ out)
{
    extern __shared__ __align__(128) uint8_t smem[];
    gemm_core(g_B, g_Wh + 3 * (size_t)DIMC * DIMC, bo, out, nullptr,
              blockIdx.y * BM, blockIdx.x * BN, smem);
}

// ---------------- tensor-core windowed attention (R7, proven) ----------------
__global__ __launch_bounds__(128) void attn_mma() {
    __shared__ __align__(128) uint8_t sQ[64 * 128];
    __shared__ __align__(128) uint8_t sK[64 * 128];
    __shared__ __align__(128) uint8_t sV[64 * 128];
    __shared__ float sS[64 * 66];

    const int b = blockIdx.x, h = blockIdx.y;
    const int tid = threadIdx.x, warp = tid >> 5, lane = tid & 31;
    const size_t base = (size_t)(b * NTOK) * DIMC + h * 64;

    const uint32_t qb = (uint32_t)__cvta_generic_to_shared(sQ);
    const uint32_t kb = (uint32_t)__cvta_generic_to_shared(sK);
    const uint32_t vb = (uint32_t)__cvta_generic_to_shared(sV);

    for (int t = tid; t < NTOK * 8; t += 128) {
        int r = t >> 3, g = t & 7;
        uint32_t off = (uint32_t)(r * 128 + ((g ^ (r & 7)) << 4));
        *(uint4*)(sQ + off) = *(const uint4*)&g_Q[base + (size_t)r * DIMC + g * 8];
        *(uint4*)(sK + off) = *(const uint4*)&g_K[base + (size_t)r * DIMC + g * 8];
        *(uint4*)(sV + off) = *(const uint4*)&g_V[base + (size_t)r * DIMC + g * 8];
    }
    for (int t = tid; t < 15 * 8; t += 128) {
        int r = NTOK + (t >> 3), g = t & 7;
        uint32_t off = (uint32_t)(r * 128 + ((g ^ (r & 7)) << 4));
        *(uint4*)(sV + off) = make_uint4(0, 0, 0, 0);
    }
    __syncthreads();

    const int lane_r = lane & 15, halfA = lane >> 4;
    const int quad = lane >> 3, gsel = quad & 1, rsel = quad >> 1;
    const int r8 = lane >> 2, cp2 = (lane & 3) * 2;
    const int swA = lane_r & 7, sw8 = lane & 7;

    {
        float acc[8][4];
#pragma unroll
        for (int nt = 0; nt < 8; ++nt)
#pragma unroll
            for (int c = 0; c < 4; ++c) acc[nt][c] = 0.f;

        const uint32_t aRowOff = qb + (uint32_t)((16 * warp + lane_r) * 128);
        uint32_t bRowOff[4];
#pragma unroll
        for (int pj = 0; pj < 4; ++pj)
            bRowOff[pj] = kb + (uint32_t)((16 * pj + rsel * 8 + sw8) * 128);

#pragma unroll
        for (int ks = 0; ks < 4; ++ks) {
            uint32_t a0, a1, a2, a3;
            ldsm_x4(a0, a1, a2, a3, aRowOff + (uint32_t)(((ks * 2 + halfA) ^ swA) << 4));
            const uint32_t gB = (uint32_t)(((ks * 2 + gsel) ^ sw8) << 4);
#pragma unroll
            for (int pj = 0; pj < 4; ++pj) {
                uint32_t b0, b1, b2, b3;
                ldsm_x4(b0, b1, b2, b3, bRowOff[pj] + gB);
                mma_f16(acc[2 * pj],     a0, a1, a2, a3, b0, b1);
                mma_f16(acc[2 * pj + 1], a0, a1, a2, a3, b2, b3);
            }
        }

        const float* gbias = g_bias + h * (NTOK * NTOK);
        const int i0 = 16 * warp + r8, i1 = i0 + 8;
#pragma unroll
        for (int nt = 0; nt < 8; ++nt) {
            int j0 = nt * 8 + cp2, j1 = j0 + 1;
            float v0 = -1e30f, v1 = -1e30f, v2 = -1e30f, v3 = -1e30f;
            if (i0 < NTOK) {
                if (j0 < NTOK) v0 = acc[nt][0] * SCALE + gbias[i0 * NTOK + j0];
                if (j1 < NTOK) v1 = acc[nt][1] * SCALE + gbias[i0 * NTOK + j1];
            }
            if (i1 < NTOK) {
                if (j0 < NTOK) v2 = acc[nt][2] * SCALE + gbias[i1 * NTOK + j0];
                if (j1 < NTOK) v3 = acc[nt][3] * SCALE + gbias[i1 * NTOK + j1];
            }
            sS[i0 * 66 + j0] = v0; sS[i0 * 66 + j1] = v1;
            sS[i1 * 66 + j0] = v2; sS[i1 * 66 + j1] = v3;
        }
    }
    __syncthreads();

    for (int i = warp; i < NTOK; i += 4) {
        float v1 = sS[i * 66 + lane];
        float v2 = sS[i * 66 + lane + 32];
        float m = fmaxf(v1, v2);
#pragma unroll
        for (int o = 16; o > 0; o >>= 1) m = fmaxf(m, __shfl_xor_sync(0xFFFFFFFFu, m, o));
        float e1 = __expf(v1 - m), e2 = __expf(v2 - m);
        float s = e1 + e2;
#pragma unroll
        for (int o = 16; o > 0; o >>= 1) s += __shfl_xor_sync(0xFFFFFFFFu, s, o);
        float inv = 1.f / s;
        __half p1 = __float2half_rn(e1 * inv);
        __half p2 = __float2half_rn(e2 * inv);
        int j1 = lane, j2 = lane + 32;
        *(__half*)(sQ + i * 128 + (((j1 >> 3) ^ (i & 7)) << 4) + (j1 & 7) * 2) = p1;
        *(__half*)(sQ + i * 128 + (((j2 >> 3) ^ (i & 7)) << 4) + (j2 & 7) * 2) = p2;
    }
    __syncthreads();

    {
        float acc[8][4];
#pragma unroll
        for (int nt = 0; nt < 8; ++nt)
#pragma unroll
            for (int c = 0; c < 4; ++c) acc[nt][c] = 0.f;

        const uint32_t aRowOff = qb + (uint32_t)((16 * warp + lane_r) * 128);

#pragma unroll
        for (int ks = 0; ks < 4; ++ks) {
            uint32_t a0, a1, a2, a3;
            ldsm_x4(a0, a1, a2, a3, aRowOff + (uint32_t)(((ks * 2 + halfA) ^ swA) << 4));
            const uint32_t tRow = (uint32_t)(16 * ks + 8 * gsel + sw8);
            const uint32_t vRow = vb + tRow * 128;
#pragma unroll
            for (int pj = 0; pj < 4; ++pj) {
                uint32_t b0, b1, b2, b3;
                ldsm_x4_t(b0, b1, b2, b3, vRow + (uint32_t)((((2 * pj + rsel) ^ sw8) << 4)));
                mma_f16(acc[2 * pj],     a0, a1, a2, a3, b0, b1);
                mma_f16(acc[2 * pj + 1], a0, a1, a2, a3, b2, b3);
            }
        }

        const int i0 = 16 * warp + r8, i1 = i0 + 8;
#pragma unroll
        for (int nt = 0; nt < 8; ++nt) {
            int d = nt * 8 + cp2;
            if (i0 < NTOK) {
                __half2 o = __floats2half2_rn(acc[nt][0], acc[nt][1]);
                *(__half2*)&g_B[base + (size_t)i0 * DIMC + d] = o;
            }
            if (i1 < NTOK) {
                __half2 o = __floats2half2_rn(acc[nt][2], acc[nt][3]);
                *(__half2*)&g_B[base + (size_t)i1 * DIMC + d] = o;
            }
        }
    }
}

// ---------------- launch ----------------
extern "C" void kernel_launch(void* const* d_in, const int* in_sizes, int n_in,
                              void* d_out, int out_size) {
    const float* landmark = (const float*)d_in[0];
    const float* image    = (const float*)d_in[1];
    const float* Wq = (const float*)d_in[2];
    const float* bq = (const float*)d_in[3];
    const float* Wk = (const float*)d_in[4];
    const float* bk = (const float*)d_in[5];
    const float* Wv = (const float*)d_in[6];
    const float* bv = (const float*)d_in[7];
    const float* Wo = (const float*)d_in[8];
    const float* bo = (const float*)d_in[9];
    const float* bt = (const float*)d_in[10];
    const int*   ri = (const int*)d_in[11];
    float* out = (float*)d_out;

    cudaFuncSetAttribute(gemm_qkv, cudaFuncAttributeMaxDynamicSharedMemorySize, SMEMSZ);
    cudaFuncSetAttribute(gemm_o,   cudaFuncAttributeMaxDynamicSharedMemorySize, SMEMSZ);

    dim3 gq(DIMC / BN, MROWS / BM, 3);   // (8, 392, 3)
    dim3 go(DIMC / BN, MROWS / BM);      // (8, 392)

    f2h_inputs<<<8192, 256>>>(landmark, image);
    f2h_weights_bias<<<512, 256>>>(Wq, Wk, Wv, Wo, bt, ri);
    gemm_qkv<<<gq, 256, SMEMSZ>>>(bq, bk, bv);           // Q,K,V in one launch
    attn_mma<<<dim3(BATCH, HEADS), 128>>>();
    gemm_o<<<go, 256, SMEMSZ>>>(bo, out);                // O
}

// round 12
// speedup vs baseline: 1.4760x; 1.0815x over previous
#include <cuda_runtime.h>
#include <cuda_fp16.h>
#include <cstdint>

#define DIMC   1024
#define HEADS  16
#define NTOK   49
#define BATCH  1024
#define MROWS  (BATCH * NTOK)   // 50176
#define SCALE  0.125f

// ---------------- half scratch ----------------
__device__ __half g_A[(size_t)MROWS * DIMC];
__device__ __half g_B[(size_t)MROWS * DIMC];
__device__ __half g_Q[(size_t)MROWS * DIMC];
__device__ __half g_K[(size_t)MROWS * DIMC];
__device__ __half g_V[(size_t)MROWS * DIMC];
__device__ __half g_Wh[4 * (size_t)DIMC * DIMC];
__device__ float  g_bias[HEADS * NTOK * NTOK];

// ---------------- conversions ----------------
__global__ void f2h_inputs(const float* __restrict__ a, const float* __restrict__ b) {
    const int n4 = MROWS * DIMC / 4;
    int i = blockIdx.x * blockDim.x + threadIdx.x;
    int stride = gridDim.x * blockDim.x;
    for (int t = i; t < n4; t += stride) {
        float4 v = ((const float4*)a)[t];
        __half2 h0 = __floats2half2_rn(v.x, v.y), h1 = __floats2half2_rn(v.z, v.w);
        ((uint2*)g_A)[t] = make_uint2(*(uint32_t*)&h0, *(uint32_t*)&h1);
        v = ((const float4*)b)[t];
        h0 = __floats2half2_rn(v.x, v.y); h1 = __floats2half2_rn(v.z, v.w);
        ((uint2*)g_B)[t] = make_uint2(*(uint32_t*)&h0, *(uint32_t*)&h1);
    }
}

__global__ void f2h_weights_bias(const float* __restrict__ w0, const float* __restrict__ w1,
                                 const float* __restrict__ w2, const float* __restrict__ w3,
                                 const float* __restrict__ bt, const int* __restrict__ ri) {
    const float* srcs[4] = {w0, w1, w2, w3};
    const int n4 = DIMC * DIMC / 4;
    int i = blockIdx.x * blockDim.x + threadIdx.x;
    int stride = gridDim.x * blockDim.x;
#pragma unroll
    for (int m = 0; m < 4; ++m) {
        const float4* src = (const float4*)srcs[m];
        uint2* dst = (uint2*)(g_Wh + (size_t)m * DIMC * DIMC);
        for (int t = i; t < n4; t += stride) {
            float4 v = src[t];
            __half2 h0 = __floats2half2_rn(v.x, v.y), h1 = __floats2half2_rn(v.z, v.w);
            dst[t] = make_uint2(*(uint32_t*)&h0, *(uint32_t*)&h1);
        }
    }
    for (int t = i; t < NTOK * NTOK; t += stride) {
        int idx = ri[t] * HEADS;
#pragma unroll
        for (int h = 0; h < HEADS; ++h)
            g_bias[h * (NTOK * NTOK) + t] = bt[idx + h];
    }
}

// ---------------- asm helpers ----------------
__device__ __forceinline__ void cp_async16(uint32_t saddr, const void* g) {
    asm volatile("cp.async.cg.shared.global [%0], [%1], 16;\n" :: "r"(saddr), "l"(g) : "memory");
}
__device__ __forceinline__ void cp_commit() { asm volatile("cp.async.commit_group;\n" ::: "memory"); }
__device__ __forceinline__ void cp_wait1() { asm volatile("cp.async.wait_group 1;\n" ::: "memory"); }

__device__ __forceinline__ void mma_f16(float c[4], uint32_t a0, uint32_t a1, uint32_t a2,
                                        uint32_t a3, uint32_t b0, uint32_t b1) {
    asm volatile(
        "mma.sync.aligned.m16n8k16.row.col.f32.f16.f16.f32 "
        "{%0,%1,%2,%3}, {%4,%5,%6,%7}, {%8,%9}, {%0,%1,%2,%3};\n"
        : "+f"(c[0]), "+f"(c[1]), "+f"(c[2]), "+f"(c[3])
        : "r"(a0), "r"(a1), "r"(a2), "r"(a3), "r"(b0), "r"(b1));
}

__device__ __forceinline__ void ldsm_x4(uint32_t& r0, uint32_t& r1, uint32_t& r2, uint32_t& r3,
                                        uint32_t addr) {
    asm volatile("ldmatrix.sync.aligned.m8n8.x4.shared.b16 {%0,%1,%2,%3}, [%4];"
                 : "=r"(r0), "=r"(r1), "=r"(r2), "=r"(r3) : "r"(addr));
}
__device__ __forceinline__ void ldsm_x4_t(uint32_t& r0, uint32_t& r1, uint32_t& r2, uint32_t& r3,
                                          uint32_t addr) {
    asm volatile("ldmatrix.sync.aligned.m8n8.x4.trans.shared.b16 {%0,%1,%2,%3}, [%4];"
                 : "=r"(r0), "=r"(r1), "=r"(r2), "=r"(r3) : "r"(addr));
}

// ---------------- FP16 GEMM core (R5/R6 proven shape, unchanged) ----------------
#define BM 128
#define BN 128
#define BKH 64
#define NKT (DIMC / BKH)           // 16
#define TILE_A (BM * 128)          // 16384 B
#define SLOT (2 * TILE_A)
#define SMEMSZ (3 * SLOT)          // 98304 B

__device__ __forceinline__ void gemm_core(
    const __half* __restrict__ X, const __half* __restrict__ W,
    const float* __restrict__ bias, float* __restrict__ Yf, __half* __restrict__ Yh,
    int m0, int n0, uint8_t* smem)
{
    const int tid = threadIdx.x, wid = tid >> 5, lane = tid & 31;
    const int wm = wid >> 2, wn = wid & 3;
    const uint32_t sbase = (uint32_t)__cvta_generic_to_shared(smem);

    float acc[4][4][4];
#pragma unroll
    for (int a = 0; a < 4; ++a)
#pragma unroll
        for (int b = 0; b < 4; ++b)
#pragma unroll
            for (int c = 0; c < 4; ++c) acc[a][b][c] = 0.f;

    const int lane_r = lane & 15;
    const int halfA  = lane >> 4;
    const int swA    = lane_r & 7;
    uint32_t offA[4];
#pragma unroll
    for (int mi = 0; mi < 4; ++mi)
        offA[mi] = (uint32_t)((wm * 64 + mi * 16 + lane_r) * 128);

    const int quad = lane >> 3;
    const int swB  = lane & 7;
    const int gselB = quad & 1;
    uint32_t offB[2];
#pragma unroll
    for (int pi = 0; pi < 2; ++pi)
        offB[pi] = (uint32_t)((wn * 32 + (2 * pi + (quad >> 1)) * 8 + (lane & 7)) * 128);

    const int row = tid >> 1;
    const int g0 = (tid & 1) * 4;
    const int swr = row & 7;
    auto load_stage = [&](int slot, int kt) {
        const __half* xa = X + (size_t)(m0 + row) * DIMC + kt * BKH;
        const __half* xb = W + (size_t)(n0 + row) * DIMC + kt * BKH;
        uint32_t sa = sbase + slot * SLOT + row * 128;
        uint32_t sb = sa + TILE_A;
#pragma unroll
        for (int q = 0; q < 4; ++q) {
            int g = g0 + q;
            uint32_t off = (uint32_t)((g ^ swr) << 4);
            cp_async16(sa + off, xa + g * 8);
            cp_async16(sb + off, xb + g * 8);
        }
        cp_commit();
    };

    load_stage(0, 0);
    load_stage(1, 1);

    const int r8 = lane >> 2, cp2 = (lane & 3) * 2;

    for (int kt = 0; kt < NKT; ++kt) {
        cp_wait1();
        __syncthreads();
        if (kt + 2 < NKT) load_stage((kt + 2) % 3, kt + 2);

        const uint32_t baseA = sbase + (kt % 3) * SLOT;
        const uint32_t baseB = baseA + TILE_A;
#pragma unroll
        for (int ks = 0; ks < 4; ++ks) {
            uint32_t a[4][4], b[2][4];
            const uint32_t gA = (uint32_t)(((ks * 2 + halfA) ^ swA) << 4);
            const uint32_t gB = (uint32_t)(((ks * 2 + gselB) ^ swB) << 4);
#pragma unroll
            for (int mi = 0; mi < 4; ++mi)
                ldsm_x4(a[mi][0], a[mi][1], a[mi][2], a[mi][3], baseA + offA[mi] + gA);
#pragma unroll
            for (int pi = 0; pi < 2; ++pi)
                ldsm_x4(b[pi][0], b[pi][1], b[pi][2], b[pi][3], baseB + offB[pi] + gB);
#pragma unroll
            for (int mi = 0; mi < 4; ++mi) {
                mma_f16(acc[mi][0], a[mi][0], a[mi][1], a[mi][2], a[mi][3], b[0][0], b[0][1]);
                mma_f16(acc[mi][1], a[mi][0], a[mi][1], a[mi][2], a[mi][3], b[0][2], b[0][3]);
                mma_f16(acc[mi][2], a[mi][0], a[mi][1], a[mi][2], a[mi][3], b[1][0], b[1][1]);
                mma_f16(acc[mi][3], a[mi][0], a[mi][1], a[mi][2], a[mi][3], b[1][2], b[1][3]);
            }
        }
    }

#pragma unroll
    for (int mi = 0; mi < 4; ++mi) {
        int r = m0 + wm * 64 + mi * 16 + r8;
#pragma unroll
        for (int ni = 0; ni < 4; ++ni) {
            int cc = n0 + wn * 32 + ni * 8 + cp2;
            float b0 = bias[cc], b1 = bias[cc + 1];
            float v0 = acc[mi][ni][0] + b0, v1 = acc[mi][ni][1] + b1;
            float v2 = acc[mi][ni][2] + b0, v3 = acc[mi][ni][3] + b1;
            if (Yf) {
                *(float2*)&Yf[(size_t)r * DIMC + cc]       = make_float2(v0, v1);
                *(float2*)&Yf[(size_t)(r + 8) * DIMC + cc] = make_float2(v2, v3);
            } else {
                __half2 h0 = __floats2half2_rn(v0, v1);
                __half2 h1 = __floats2half2_rn(v2, v3);
                *(__half2*)&Yh[(size_t)r * DIMC + cc]       = h0;
                *(__half2*)&Yh[(size_t)(r + 8) * DIMC + cc] = h1;
            }
        }
    }
}

__global__ __launch_bounds__(256, 2) void gemm_qkv(
    const float* __restrict__ bq, const float* __restrict__ bk, const float* __restrict__ bv)
{
    extern __shared__ __align__(128) uint8_t smem[];
    const int z = blockIdx.z;
    const __half* X = (z == 0) ? g_A : g_B;
    const __half* W = g_Wh + (size_t)z * DIMC * DIMC;
    __half* Yh = (z == 0) ? g_Q : (z == 1) ? g_K : g_V;
    const float* bias = (z == 0) ? bq : (z == 1) ? bk : bv;
    gemm_core(X, W, bias, nullptr, Yh, blockIdx.y * BM, blockIdx.x * BN, smem);
}

__global__ __launch_bounds__(256, 2) void gemm_o(
    const float* __restrict__ bo, float* __restrict__ out)
{
    extern __shared__ __align__(128) uint8_t smem[];
    gemm_core(g_B, g_Wh + 3 * (size_t)DIMC * DIMC, bo, out, nullptr,
              blockIdx.y * BM, blockIdx.x * BN, smem);
}

// ---------------- attention: register-resident softmax (flash-style frag pass) ----------------
__global__ __launch_bounds__(128) void attn_mma() {
    __shared__ __align__(128) uint8_t sQ[64 * 128];
    __shared__ __align__(128) uint8_t sK[64 * 128];
    __shared__ __align__(128) uint8_t sV[64 * 128];

    const int b = blockIdx.x, h = blockIdx.y;
    const int tid = threadIdx.x, warp = tid >> 5, lane = tid & 31;
    const size_t base = (size_t)(b * NTOK) * DIMC + h * 64;

    const uint32_t qb = (uint32_t)__cvta_generic_to_shared(sQ);
    const uint32_t kb = (uint32_t)__cvta_generic_to_shared(sK);
    const uint32_t vb = (uint32_t)__cvta_generic_to_shared(sV);

    for (int t = tid; t < NTOK * 8; t += 128) {
        int r = t >> 3, g = t & 7;
        uint32_t off = (uint32_t)(r * 128 + ((g ^ (r & 7)) << 4));
        *(uint4*)(sQ + off) = *(const uint4*)&g_Q[base + (size_t)r * DIMC + g * 8];
        *(uint4*)(sK + off) = *(const uint4*)&g_K[base + (size_t)r * DIMC + g * 8];
        *(uint4*)(sV + off) = *(const uint4*)&g_V[base + (size_t)r * DIMC + g * 8];
    }
    // zero V pad rows (P=0 times NaN-garbage would still poison; keep zeros)
    for (int t = tid; t < 15 * 8; t += 128) {
        int r = NTOK + (t >> 3), g = t & 7;
        uint32_t off = (uint32_t)(r * 128 + ((g ^ (r & 7)) << 4));
        *(uint4*)(sV + off) = make_uint4(0, 0, 0, 0);
    }
    __syncthreads();

    const int lane_r = lane & 15, halfA = lane >> 4;
    const int quad = lane >> 3, gsel = quad & 1, rsel = quad >> 1;
    const int r8 = lane >> 2, cp2 = (lane & 3) * 2;
    const int swA = lane_r & 7, sw8 = lane & 7;

    // ---- QK^T ----
    float acc[8][4];
#pragma unroll
    for (int nt = 0; nt < 8; ++nt)
#pragma unroll
        for (int c = 0; c < 4; ++c) acc[nt][c] = 0.f;

    const uint32_t aRowOff = qb + (uint32_t)((16 * warp + lane_r) * 128);
    uint32_t bRowOff[4];
#pragma unroll
    for (int pj = 0; pj < 4; ++pj)
        bRowOff[pj] = kb + (uint32_t)((16 * pj + rsel * 8 + sw8) * 128);

#pragma unroll
    for (int ks = 0; ks < 4; ++ks) {
        uint32_t a0, a1, a2, a3;
        ldsm_x4(a0, a1, a2, a3, aRowOff + (uint32_t)(((ks * 2 + halfA) ^ swA) << 4));
        const uint32_t gB = (uint32_t)(((ks * 2 + gsel) ^ sw8) << 4);
#pragma unroll
        for (int pj = 0; pj < 4; ++pj) {
            uint32_t b0, b1, b2, b3;
            ldsm_x4(b0, b1, b2, b3, bRowOff[pj] + gB);
            mma_f16(acc[2 * pj],     a0, a1, a2, a3, b0, b1);
            mma_f16(acc[2 * pj + 1], a0, a1, a2, a3, b2, b3);
        }
    }

    // ---- mask + scale + bias in registers ----
    const float* gbias = g_bias + h * (NTOK * NTOK);
    const int i0 = 16 * warp + r8, i1 = i0 + 8;
    const bool ri0 = (i0 < NTOK), ri1 = (i1 < NTOK);
#pragma unroll
    for (int nt = 0; nt < 8; ++nt) {
        int j0 = nt * 8 + cp2, j1 = j0 + 1;
        acc[nt][0] = (ri0 && j0 < NTOK) ? acc[nt][0] * SCALE + gbias[i0 * NTOK + j0] : -1e30f;
        acc[nt][1] = (ri0 && j1 < NTOK) ? acc[nt][1] * SCALE + gbias[i0 * NTOK + j1] : -1e30f;
        acc[nt][2] = (ri1 && j0 < NTOK) ? acc[nt][2] * SCALE + gbias[i1 * NTOK + j0] : -1e30f;
        acc[nt][3] = (ri1 && j1 < NTOK) ? acc[nt][3] * SCALE + gbias[i1 * NTOK + j1] : -1e30f;
    }

    // ---- register softmax: rows i0 (c0,c1) and i1 (c2,c3), quad = 4 lanes ----
    float m0 = -1e30f, m1 = -1e30f;
#pragma unroll
    for (int nt = 0; nt < 8; ++nt) {
        m0 = fmaxf(m0, fmaxf(acc[nt][0], acc[nt][1]));
        m1 = fmaxf(m1, fmaxf(acc[nt][2], acc[nt][3]));
    }
    m0 = fmaxf(m0, __shfl_xor_sync(0xFFFFFFFFu, m0, 1));
    m0 = fmaxf(m0, __shfl_xor_sync(0xFFFFFFFFu, m0, 2));
    m1 = fmaxf(m1, __shfl_xor_sync(0xFFFFFFFFu, m1, 1));
    m1 = fmaxf(m1, __shfl_xor_sync(0xFFFFFFFFu, m1, 2));

    float s0 = 0.f, s1 = 0.f;
#pragma unroll
    for (int nt = 0; nt < 8; ++nt) {
        acc[nt][0] = __expf(acc[nt][0] - m0); s0 += acc[nt][0];
        acc[nt][1] = __expf(acc[nt][1] - m0); s0 += acc[nt][1];
        acc[nt][2] = __expf(acc[nt][2] - m1); s1 += acc[nt][2];
        acc[nt][3] = __expf(acc[nt][3] - m1); s1 += acc[nt][3];
    }
    s0 += __shfl_xor_sync(0xFFFFFFFFu, s0, 1);
    s0 += __shfl_xor_sync(0xFFFFFFFFu, s0, 2);
    s1 += __shfl_xor_sync(0xFFFFFFFFu, s1, 1);
    s1 += __shfl_xor_sync(0xFFFFFFFFu, s1, 2);
    const float inv0 = 1.f / s0, inv1 = 1.f / s1;

    // ---- pack P into A-fragments: pa[ks] = {a0: (i0, k lo), a1: (i1, k lo), a2: (i0, k hi), a3: (i1, k hi)} ----
    uint32_t pa[4][4];
#pragma unroll
    for (int ks = 0; ks < 4; ++ks) {
        __half2 t0 = __floats2half2_rn(acc[2 * ks][0] * inv0,     acc[2 * ks][1] * inv0);
        __half2 t1 = __floats2half2_rn(acc[2 * ks][2] * inv1,     acc[2 * ks][3] * inv1);
        __half2 t2 = __floats2half2_rn(acc[2 * ks + 1][0] * inv0, acc[2 * ks + 1][1] * inv0);
        __half2 t3 = __floats2half2_rn(acc[2 * ks + 1][2] * inv1, acc[2 * ks + 1][3] * inv1);
        pa[ks][0] = *(uint32_t*)&t0;
        pa[ks][1] = *(uint32_t*)&t1;
        pa[ks][2] = *(uint32_t*)&t2;
        pa[ks][3] = *(uint32_t*)&t3;
    }

    // ---- PV directly from register fragments ----
    float out[8][4];
#pragma unroll
    for (int nt = 0; nt < 8; ++nt)
#pragma unroll
        for (int c = 0; c < 4; ++c) out[nt][c] = 0.f;

#pragma unroll
    for (int ks = 0; ks < 4; ++ks) {
        const uint32_t tRow = (uint32_t)(16 * ks + 8 * gsel + sw8);
        const uint32_t vRow = vb + tRow * 128;
#pragma unroll
        for (int pj = 0; pj < 4; ++pj) {
            uint32_t b0, b1, b2, b3;
            ldsm_x4_t(b0, b1, b2, b3, vRow + (uint32_t)((((2 * pj + rsel) ^ sw8) << 4)));
            mma_f16(out[2 * pj],     pa[ks][0], pa[ks][1], pa[ks][2], pa[ks][3], b0, b1);
            mma_f16(out[2 * pj + 1], pa[ks][0], pa[ks][1], pa[ks][2], pa[ks][3], b2, b3);
        }
    }

    // ---- store ----
#pragma unroll
    for (int nt = 0; nt < 8; ++nt) {
        int d = nt * 8 + cp2;
        if (ri0) {
            __half2 o = __floats2half2_rn(out[nt][0], out[nt][1]);
            *(__half2*)&g_B[base + (size_t)i0 * DIMC + d] = o;
        }
        if (ri1) {
            __half2 o = __floats2half2_rn(out[nt][2], out[nt][3]);
            *(__half2*)&g_B[base + (size_t)i1 * DIMC + d] = o;
        }
    }
}

// ---------------- launch ----------------
extern "C" void kernel_launch(void* const* d_in, const int* in_sizes, int n_in,
                              void* d_out, int out_size) {
    const float* landmark = (const float*)d_in[0];
    const float* image    = (const float*)d_in[1];
    const float* Wq = (const float*)d_in[2];
    const float* bq = (const float*)d_in[3];
    const float* Wk = (const float*)d_in[4];
    const float* bk = (const float*)d_in[5];
    const float* Wv = (const float*)d_in[6];
    const float* bv = (const float*)d_in[7];
    const float* Wo = (const float*)d_in[8];
    const float* bo = (const float*)d_in[9];
    const float* bt = (const float*)d_in[10];
    const int*   ri = (const int*)d_in[11];
    float* out = (float*)d_out;

    cudaFuncSetAttribute(gemm_qkv, cudaFuncAttributeMaxDynamicSharedMemorySize, SMEMSZ);
    cudaFuncSetAttribute(gemm_o,   cudaFuncAttributeMaxDynamicSharedMemorySize, SMEMSZ);

    dim3 gq(DIMC / BN, MROWS / BM, 3);
    dim3 go(DIMC / BN, MROWS / BM);

    f2h_inputs<<<8192, 256>>>(landmark, image);
    f2h_weights_bias<<<512, 256>>>(Wq, Wk, Wv, Wo, bt, ri);
    gemm_qkv<<<gq, 256, SMEMSZ>>>(bq, bk, bv);
    attn_mma<<<dim3(BATCH, HEADS), 128>>>();
    gemm_o<<<go, 256, SMEMSZ>>>(bo, out);
}

// round 13
// speedup vs baseline: 1.5060x; 1.0204x over previous
#include <cuda_runtime.h>
#include <cuda_fp16.h>
#include <cstdint>

#define DIMC   1024
#define HEADS  16
#define NTOK   49
#define BATCH  1024
#define MROWS  (BATCH * NTOK)   // 50176
#define SCALE  0.125f

// ---------------- half scratch ----------------
__device__ __half g_A[(size_t)MROWS * DIMC];
__device__ __half g_B[(size_t)MROWS * DIMC];
__device__ __half g_Q[(size_t)MROWS * DIMC];
__device__ __half g_K[(size_t)MROWS * DIMC];
__device__ __half g_V[(size_t)MROWS * DIMC];
__device__ __half g_Wh[4 * (size_t)DIMC * DIMC];
__device__ float  g_bias[HEADS * NTOK * NTOK];

// ---------------- fused conversion: inputs + weights + bias table ----------------
__global__ void f2h_all(const float* __restrict__ a, const float* __restrict__ b,
                        const float* __restrict__ w0, const float* __restrict__ w1,
                        const float* __restrict__ w2, const float* __restrict__ w3,
                        const float* __restrict__ bt, const int* __restrict__ ri) {
    const int n4 = MROWS * DIMC / 4;
    int i = blockIdx.x * blockDim.x + threadIdx.x;
    int stride = gridDim.x * blockDim.x;
    for (int t = i; t < n4; t += stride) {
        float4 v = ((const float4*)a)[t];
        __half2 h0 = __floats2half2_rn(v.x, v.y), h1 = __floats2half2_rn(v.z, v.w);
        ((uint2*)g_A)[t] = make_uint2(*(uint32_t*)&h0, *(uint32_t*)&h1);
        v = ((const float4*)b)[t];
        h0 = __floats2half2_rn(v.x, v.y); h1 = __floats2half2_rn(v.z, v.w);
        ((uint2*)g_B)[t] = make_uint2(*(uint32_t*)&h0, *(uint32_t*)&h1);
    }
    const float* srcs[4] = {w0, w1, w2, w3};
    const int w4 = DIMC * DIMC / 4;
#pragma unroll
    for (int m = 0; m < 4; ++m) {
        const float4* src = (const float4*)srcs[m];
        uint2* dst = (uint2*)(g_Wh + (size_t)m * DIMC * DIMC);
        for (int t = i; t < w4; t += stride) {
            float4 v = src[t];
            __half2 h0 = __floats2half2_rn(v.x, v.y), h1 = __floats2half2_rn(v.z, v.w);
            dst[t] = make_uint2(*(uint32_t*)&h0, *(uint32_t*)&h1);
        }
    }
    for (int t = i; t < NTOK * NTOK; t += stride) {
        int idx = ri[t] * HEADS;
#pragma unroll
        for (int h = 0; h < HEADS; ++h)
            g_bias[h * (NTOK * NTOK) + t] = bt[idx + h];
    }
}

// ---------------- asm helpers ----------------
__device__ __forceinline__ void cp_async16(uint32_t saddr, const void* g) {
    asm volatile("cp.async.cg.shared.global [%0], [%1], 16;\n" :: "r"(saddr), "l"(g) : "memory");
}
__device__ __forceinline__ void cp_commit() { asm volatile("cp.async.commit_group;\n" ::: "memory"); }
__device__ __forceinline__ void cp_wait1() { asm volatile("cp.async.wait_group 1;\n" ::: "memory"); }
__device__ __forceinline__ void cp_wait0() { asm volatile("cp.async.wait_group 0;\n" ::: "memory"); }

__device__ __forceinline__ void mma_f16(float c[4], uint32_t a0, uint32_t a1, uint32_t a2,
                                        uint32_t a3, uint32_t b0, uint32_t b1) {
    asm volatile(
        "mma.sync.aligned.m16n8k16.row.col.f32.f16.f16.f32 "
        "{%0,%1,%2,%3}, {%4,%5,%6,%7}, {%8,%9}, {%0,%1,%2,%3};\n"
        : "+f"(c[0]), "+f"(c[1]), "+f"(c[2]), "+f"(c[3])
        : "r"(a0), "r"(a1), "r"(a2), "r"(a3), "r"(b0), "r"(b1));
}

__device__ __forceinline__ void ldsm_x4(uint32_t& r0, uint32_t& r1, uint32_t& r2, uint32_t& r3,
                                        uint32_t addr) {
    asm volatile("ldmatrix.sync.aligned.m8n8.x4.shared.b16 {%0,%1,%2,%3}, [%4];"
                 : "=r"(r0), "=r"(r1), "=r"(r2), "=r"(r3) : "r"(addr));
}
__device__ __forceinline__ void ldsm_x4_t(uint32_t& r0, uint32_t& r1, uint32_t& r2, uint32_t& r3,
                                          uint32_t addr) {
    asm volatile("ldmatrix.sync.aligned.m8n8.x4.trans.shared.b16 {%0,%1,%2,%3}, [%4];"
                 : "=r"(r0), "=r"(r1), "=r"(r2), "=r"(r3) : "r"(addr));
}

// ---------------- FP16 GEMM core (proven shape, FROZEN) ----------------
#define BM 128
#define BN 128
#define BKH 64
#define NKT (DIMC / BKH)           // 16
#define TILE_A (BM * 128)          // 16384 B
#define SLOT (2 * TILE_A)
#define SMEMSZ (3 * SLOT)          // 98304 B

__device__ __forceinline__ void gemm_core(
    const __half* __restrict__ X, const __half* __restrict__ W,
    const float* __restrict__ bias, float* __restrict__ Yf, __half* __restrict__ Yh,
    int m0, int n0, uint8_t* smem)
{
    const int tid = threadIdx.x, wid = tid >> 5, lane = tid & 31;
    const int wm = wid >> 2, wn = wid & 3;
    const uint32_t sbase = (uint32_t)__cvta_generic_to_shared(smem);

    float acc[4][4][4];
#pragma unroll
    for (int a = 0; a < 4; ++a)
#pragma unroll
        for (int b = 0; b < 4; ++b)
#pragma unroll
            for (int c = 0; c < 4; ++c) acc[a][b][c] = 0.f;

    const int lane_r = lane & 15;
    const int halfA  = lane >> 4;
    const int swA    = lane_r & 7;
    uint32_t offA[4];
#pragma unroll
    for (int mi = 0; mi < 4; ++mi)
        offA[mi] = (uint32_t)((wm * 64 + mi * 16 + lane_r) * 128);

    const int quad = lane >> 3;
    const int swB  = lane & 7;
    const int gselB = quad & 1;
    uint32_t offB[2];
#pragma unroll
    for (int pi = 0; pi < 2; ++pi)
        offB[pi] = (uint32_t)((wn * 32 + (2 * pi + (quad >> 1)) * 8 + (lane & 7)) * 128);

    const int row = tid >> 1;
    const int g0 = (tid & 1) * 4;
    const int swr = row & 7;
    auto load_stage = [&](int slot, int kt) {
        const __half* xa = X + (size_t)(m0 + row) * DIMC + kt * BKH;
        const __half* xb = W + (size_t)(n0 + row) * DIMC + kt * BKH;
        uint32_t sa = sbase + slot * SLOT + row * 128;
        uint32_t sb = sa + TILE_A;
#pragma unroll
        for (int q = 0; q < 4; ++q) {
            int g = g0 + q;
            uint32_t off = (uint32_t)((g ^ swr) << 4);
            cp_async16(sa + off, xa + g * 8);
            cp_async16(sb + off, xb + g * 8);
        }
        cp_commit();
    };

    load_stage(0, 0);
    load_stage(1, 1);

    const int r8 = lane >> 2, cp2 = (lane & 3) * 2;

    for (int kt = 0; kt < NKT; ++kt) {
        cp_wait1();
        __syncthreads();
        if (kt + 2 < NKT) load_stage((kt + 2) % 3, kt + 2);

        const uint32_t baseA = sbase + (kt % 3) * SLOT;
        const uint32_t baseB = baseA + TILE_A;
#pragma unroll
        for (int ks = 0; ks < 4; ++ks) {
            uint32_t a[4][4], b[2][4];
            const uint32_t gA = (uint32_t)(((ks * 2 + halfA) ^ swA) << 4);
            const uint32_t gB = (uint32_t)(((ks * 2 + gselB) ^ swB) << 4);
#pragma unroll
            for (int mi = 0; mi < 4; ++mi)
                ldsm_x4(a[mi][0], a[mi][1], a[mi][2], a[mi][3], baseA + offA[mi] + gA);
#pragma unroll
            for (int pi = 0; pi < 2; ++pi)
                ldsm_x4(b[pi][0], b[pi][1], b[pi][2], b[pi][3], baseB + offB[pi] + gB);
#pragma unroll
            for (int mi = 0; mi < 4; ++mi) {
                mma_f16(acc[mi][0], a[mi][0], a[mi][1], a[mi][2], a[mi][3], b[0][0], b[0][1]);
                mma_f16(acc[mi][1], a[mi][0], a[mi][1], a[mi][2], a[mi][3], b[0][2], b[0][3]);
                mma_f16(acc[mi][2], a[mi][0], a[mi][1], a[mi][2], a[mi][3], b[1][0], b[1][1]);
                mma_f16(acc[mi][3], a[mi][0], a[mi][1], a[mi][2], a[mi][3], b[1][2], b[1][3]);
            }
        }
    }

#pragma unroll
    for (int mi = 0; mi < 4; ++mi) {
        int r = m0 + wm * 64 + mi * 16 + r8;
#pragma unroll
        for (int ni = 0; ni < 4; ++ni) {
            int cc = n0 + wn * 32 + ni * 8 + cp2;
            float b0 = bias[cc], b1 = bias[cc + 1];
            float v0 = acc[mi][ni][0] + b0, v1 = acc[mi][ni][1] + b1;
            float v2 = acc[mi][ni][2] + b0, v3 = acc[mi][ni][3] + b1;
            if (Yf) {
                *(float2*)&Yf[(size_t)r * DIMC + cc]       = make_float2(v0, v1);
                *(float2*)&Yf[(size_t)(r + 8) * DIMC + cc] = make_float2(v2, v3);
            } else {
                __half2 h0 = __floats2half2_rn(v0, v1);
                __half2 h1 = __floats2half2_rn(v2, v3);
                *(__half2*)&Yh[(size_t)r * DIMC + cc]       = h0;
                *(__half2*)&Yh[(size_t)(r + 8) * DIMC + cc] = h1;
            }
        }
    }
}

__global__ __launch_bounds__(256, 2) void gemm_qkv(
    const float* __restrict__ bq, const float* __restrict__ bk, const float* __restrict__ bv)
{
    extern __shared__ __align__(128) uint8_t smem[];
    const int z = blockIdx.z;
    const __half* X = (z == 0) ? g_A : g_B;
    const __half* W = g_Wh + (size_t)z * DIMC * DIMC;
    __half* Yh = (z == 0) ? g_Q : (z == 1) ? g_K : g_V;
    const float* bias = (z == 0) ? bq : (z == 1) ? bk : bv;
    gemm_core(X, W, bias, nullptr, Yh, blockIdx.y * BM, blockIdx.x * BN, smem);
}

__global__ __launch_bounds__(256, 2) void gemm_o(
    const float* __restrict__ bo, float* __restrict__ out)
{
    extern __shared__ __align__(128) uint8_t smem[];
    gemm_core(g_B, g_Wh + 3 * (size_t)DIMC * DIMC, bo, out, nullptr,
              blockIdx.y * BM, blockIdx.x * BN, smem);
}

// ---------------- attention: reg-softmax + cp.async loads ----------------
__global__ __launch_bounds__(128) void attn_mma() {
    __shared__ __align__(128) uint8_t sQ[64 * 128];
    __shared__ __align__(128) uint8_t sK[64 * 128];
    __shared__ __align__(128) uint8_t sV[64 * 128];

    const int b = blockIdx.x, h = blockIdx.y;
    const int tid = threadIdx.x, warp = tid >> 5, lane = tid & 31;
    const size_t base = (size_t)(b * NTOK) * DIMC + h * 64;

    const uint32_t qb = (uint32_t)__cvta_generic_to_shared(sQ);
    const uint32_t kb = (uint32_t)__cvta_generic_to_shared(sK);
    const uint32_t vb = (uint32_t)__cvta_generic_to_shared(sV);

    // async tile loads (49 rows x 8 granules each for Q,K,V)
    for (int t = tid; t < NTOK * 8; t += 128) {
        int r = t >> 3, g = t & 7;
        uint32_t off = (uint32_t)(r * 128 + ((g ^ (r & 7)) << 4));
        const size_t gsrc = base + (size_t)r * DIMC + g * 8;
        cp_async16(qb + off, &g_Q[gsrc]);
        cp_async16(kb + off, &g_K[gsrc]);
        cp_async16(vb + off, &g_V[gsrc]);
    }
    // zero V pad rows (overlaps with cp.async; disjoint addresses)
    for (int t = tid; t < 15 * 8; t += 128) {
        int r = NTOK + (t >> 3), g = t & 7;
        uint32_t off = (uint32_t)(r * 128 + ((g ^ (r & 7)) << 4));
        *(uint4*)(sV + off) = make_uint4(0, 0, 0, 0);
    }
    cp_commit();
    cp_wait0();
    __syncthreads();

    const int lane_r = lane & 15, halfA = lane >> 4;
    const int quad = lane >> 3, gsel = quad & 1, rsel = quad >> 1;
    const int r8 = lane >> 2, cp2 = (lane & 3) * 2;
    const int swA = lane_r & 7, sw8 = lane & 7;

    // ---- QK^T ----
    float acc[8][4];
#pragma unroll
    for (int nt = 0; nt < 8; ++nt)
#pragma unroll
        for (int c = 0; c < 4; ++c) acc[nt][c] = 0.f;

    const uint32_t aRowOff = qb + (uint32_t)((16 * warp + lane_r) * 128);
    uint32_t bRowOff[4];
#pragma unroll
    for (int pj = 0; pj < 4; ++pj)
        bRowOff[pj] = kb + (uint32_t)((16 * pj + rsel * 8 + sw8) * 128);

#pragma unroll
    for (int ks = 0; ks < 4; ++ks) {
        uint32_t a0, a1, a2, a3;
        ldsm_x4(a0, a1, a2, a3, aRowOff + (uint32_t)(((ks * 2 + halfA) ^ swA) << 4));
        const uint32_t gB = (uint32_t)(((ks * 2 + gsel) ^ sw8) << 4);
#pragma unroll
        for (int pj = 0; pj < 4; ++pj) {
            uint32_t b0, b1, b2, b3;
            ldsm_x4(b0, b1, b2, b3, bRowOff[pj] + gB);
            mma_f16(acc[2 * pj],     a0, a1, a2, a3, b0, b1);
            mma_f16(acc[2 * pj + 1], a0, a1, a2, a3, b2, b3);
        }
    }

    // ---- mask + scale + bias in registers ----
    const float* gbias = g_bias + h * (NTOK * NTOK);
    const int i0 = 16 * warp + r8, i1 = i0 + 8;
    const bool ri0 = (i0 < NTOK), ri1 = (i1 < NTOK);
#pragma unroll
    for (int nt = 0; nt < 8; ++nt) {
        int j0 = nt * 8 + cp2, j1 = j0 + 1;
        acc[nt][0] = (ri0 && j0 < NTOK) ? acc[nt][0] * SCALE + gbias[i0 * NTOK + j0] : -1e30f;
        acc[nt][1] = (ri0 && j1 < NTOK) ? acc[nt][1] * SCALE + gbias[i0 * NTOK + j1] : -1e30f;
        acc[nt][2] = (ri1 && j0 < NTOK) ? acc[nt][2] * SCALE + gbias[i1 * NTOK + j0] : -1e30f;
        acc[nt][3] = (ri1 && j1 < NTOK) ? acc[nt][3] * SCALE + gbias[i1 * NTOK + j1] : -1e30f;
    }

    // ---- register softmax across quad ----
    float m0 = -1e30f, m1 = -1e30f;
#pragma unroll
    for (int nt = 0; nt < 8; ++nt) {
        m0 = fmaxf(m0, fmaxf(acc[nt][0], acc[nt][1]));
        m1 = fmaxf(m1, fmaxf(acc[nt][2], acc[nt][3]));
    }
    m0 = fmaxf(m0, __shfl_xor_sync(0xFFFFFFFFu, m0, 1));
    m0 = fmaxf(m0, __shfl_xor_sync(0xFFFFFFFFu, m0, 2));
    m1 = fmaxf(m1, __shfl_xor_sync(0xFFFFFFFFu, m1, 1));
    m1 = fmaxf(m1, __shfl_xor_sync(0xFFFFFFFFu, m1, 2));

    float s0 = 0.f, s1 = 0.f;
#pragma unroll
    for (int nt = 0; nt < 8; ++nt) {
        acc[nt][0] = __expf(acc[nt][0] - m0); s0 += acc[nt][0];
        acc[nt][1] = __expf(acc[nt][1] - m0); s0 += acc[nt][1];
        acc[nt][2] = __expf(acc[nt][2] - m1); s1 += acc[nt][2];
        acc[nt][3] = __expf(acc[nt][3] - m1); s1 += acc[nt][3];
    }
    s0 += __shfl_xor_sync(0xFFFFFFFFu, s0, 1);
    s0 += __shfl_xor_sync(0xFFFFFFFFu, s0, 2);
    s1 += __shfl_xor_sync(0xFFFFFFFFu, s1, 1);
    s1 += __shfl_xor_sync(0xFFFFFFFFu, s1, 2);
    const float inv0 = 1.f / s0, inv1 = 1.f / s1;

    // ---- pack P into A-fragments ----
    uint32_t pa[4][4];
#pragma unroll
    for (int ks = 0; ks < 4; ++ks) {
        __half2 t0 = __floats2half2_rn(acc[2 * ks][0] * inv0,     acc[2 * ks][1] * inv0);
        __half2 t1 = __floats2half2_rn(acc[2 * ks][2] * inv1,     acc[2 * ks][3] * inv1);
        __half2 t2 = __floats2half2_rn(acc[2 * ks + 1][0] * inv0, acc[2 * ks + 1][1] * inv0);
        __half2 t3 = __floats2half2_rn(acc[2 * ks + 1][2] * inv1, acc[2 * ks + 1][3] * inv1);
        pa[ks][0] = *(uint32_t*)&t0;
        pa[ks][1] = *(uint32_t*)&t1;
        pa[ks][2] = *(uint32_t*)&t2;
        pa[ks][3] = *(uint32_t*)&t3;
    }

    // ---- PV from register fragments ----
    float out[8][4];
#pragma unroll
    for (int nt = 0; nt < 8; ++nt)
#pragma unroll
        for (int c = 0; c < 4; ++c) out[nt][c] = 0.f;

#pragma unroll
    for (int ks = 0; ks < 4; ++ks) {
        const uint32_t tRow = (uint32_t)(16 * ks + 8 * gsel + sw8);
        const uint32_t vRow = vb + tRow * 128;
#pragma unroll
        for (int pj = 0; pj < 4; ++pj) {
            uint32_t b0, b1, b2, b3;
            ldsm_x4_t(b0, b1, b2, b3, vRow + (uint32_t)((((2 * pj + rsel) ^ sw8) << 4)));
            mma_f16(out[2 * pj],     pa[ks][0], pa[ks][1], pa[ks][2], pa[ks][3], b0, b1);
            mma_f16(out[2 * pj + 1], pa[ks][0], pa[ks][1], pa[ks][2], pa[ks][3], b2, b3);
        }
    }

    // ---- store ----
#pragma unroll
    for (int nt = 0; nt < 8; ++nt) {
        int d = nt * 8 + cp2;
        if (ri0) {
            __half2 o = __floats2half2_rn(out[nt][0], out[nt][1]);
            *(__half2*)&g_B[base + (size_t)i0 * DIMC + d] = o;
        }
        if (ri1) {
            __half2 o = __floats2half2_rn(out[nt][2], out[nt][3]);
            *(__half2*)&g_B[base + (size_t)i1 * DIMC + d] = o;
        }
    }
}

// ---------------- launch ----------------
extern "C" void kernel_launch(void* const* d_in, const int* in_sizes, int n_in,
                              void* d_out, int out_size) {
    const float* landmark = (const float*)d_in[0];
    const float* image    = (const float*)d_in[1];
    const float* Wq = (const float*)d_in[2];
    const float* bq = (const float*)d_in[3];
    const float* Wk = (const float*)d_in[4];
    const float* bk = (const float*)d_in[5];
    const float* Wv = (const float*)d_in[6];
    const float* bv = (const float*)d_in[7];
    const float* Wo = (const float*)d_in[8];
    const float* bo = (const float*)d_in[9];
    const float* bt = (const float*)d_in[10];
    const int*   ri = (const int*)d_in[11];
    float* out = (float*)d_out;

    cudaFuncSetAttribute(gemm_qkv, cudaFuncAttributeMaxDynamicSharedMemorySize, SMEMSZ);
    cudaFuncSetAttribute(gemm_o,   cudaFuncAttributeMaxDynamicSharedMemorySize, SMEMSZ);

    dim3 gq(DIMC / BN, MROWS / BM, 3);
    dim3 go(DIMC / BN, MROWS / BM);

    f2h_all<<<8192, 256>>>(landmark, image, Wq, Wk, Wv, Wo, bt, ri);
    gemm_qkv<<<gq, 256, SMEMSZ>>>(bq, bk, bv);
    attn_mma<<<dim3(BATCH, HEADS), 128>>>();
    gemm_o<<<go, 256, SMEMSZ>>>(bo, out);
}